// round 2
// baseline (speedup 1.0000x reference)
#include <cuda_runtime.h>
#include <math.h>

#define NUM_WIRES 18
#define BATCH     64
#define DIM       262144            // 2^18
#define CHUNK_BITS 14
#define CHUNK     16384             // 2^14
#define NCHUNK    16                // 2^(18-14)
#define PL_THREADS 512
#define PH_THREADS 256

// Ping-pong state buffers (128MB each). __device__ globals are the sanctioned scratch.
__device__ float2 g_buf0[BATCH * DIM];
__device__ float2 g_buf1[BATCH * DIM];
// Gate table: per (layer, wire): (cos(ty/2), sin(ty/2), cos(tz/2), sin(tz/2))
__device__ float4 g_gates[3 * NUM_WIRES];
// Expval partials: [batch][chunk][wire]
__device__ float g_partial[BATCH * NCHUNK * NUM_WIRES];

// ---------------------------------------------------------------------------
// helpers
// ---------------------------------------------------------------------------

// Apply fused RZ(tz)*RY(ty) to amplitude pair (a = bit0 branch, b = bit1 branch)
__device__ __forceinline__ void apply_gate(float2& a, float2& b, float4 g) {
    // RY: a' = c*a - s*b ; b' = s*a + c*b        (c=g.x, s=g.y, real)
    float ar = fmaf(g.x, a.x, -g.y * b.x);
    float ai = fmaf(g.x, a.y, -g.y * b.y);
    float br = fmaf(g.y, a.x,  g.x * b.x);
    float bi = fmaf(g.y, a.y,  g.x * b.y);
    // RZ: a'' = a' * (cz - i sz) ; b'' = b' * (cz + i sz)   (cz=g.z, sz=g.w)
    a.x = fmaf(g.z, ar,  g.w * ai);
    a.y = fmaf(g.z, ai, -g.w * ar);
    b.x = fmaf(g.z, br, -g.w * bi);
    b.y = fmaf(g.z, bi,  g.w * br);
}

// shared-memory XOR swizzle (kills bank conflicts for all stage patterns)
__device__ __forceinline__ int SW(int t) { return t ^ ((t >> 5) & 31); }

// inverse Gray code (prefix-xor from MSB) for values < 2^16
__device__ __forceinline__ int invgray(int t) {
    t ^= t >> 1; t ^= t >> 2; t ^= t >> 4; t ^= t >> 8;
    return t;
}

// ---------------------------------------------------------------------------
// prep: compute gate coefficient table from params (3,2,18)
// ---------------------------------------------------------------------------
__global__ void k_prep(const float* __restrict__ params) {
    int t = threadIdx.x;
    if (t < 3 * NUM_WIRES) {
        int layer = t / NUM_WIRES, w = t % NUM_WIRES;
        float ty = params[(layer * 2 + 0) * NUM_WIRES + w] * 0.5f;
        float tz = params[(layer * 2 + 1) * NUM_WIRES + w] * 0.5f;
        g_gates[t] = make_float4(cosf(ty), sinf(ty), cosf(tz), sinf(tz));
    }
}

// ---------------------------------------------------------------------------
// pass_high: gates on wires 0..3 (index bits 17..14). Register-only, in-place.
// Each thread owns 16 amplitudes strided by 2^14.
// ---------------------------------------------------------------------------
__global__ void __launch_bounds__(PH_THREADS)
k_pass_high(float2* __restrict__ buf, int layer) {
    int gid = blockIdx.x * blockDim.x + threadIdx.x;   // 64 * 2^14 threads
    int b = gid >> CHUNK_BITS;
    int u = gid & (CHUNK - 1);
    long base = (long)b * DIM + u;

    float2 x[16];
#pragma unroll
    for (int r = 0; r < 16; ++r) x[r] = buf[base + ((long)r << CHUNK_BITS)];

#pragma unroll
    for (int w = 0; w < 4; ++w) {
        float4 g = g_gates[layer * NUM_WIRES + w];
        int m = 8 >> w;                      // wire w <-> r-bit (3-w)
#pragma unroll
        for (int r = 0; r < 16; ++r)
            if (!(r & m)) apply_gate(x[r], x[r | m], g);
    }

#pragma unroll
    for (int r = 0; r < 16; ++r) buf[base + ((long)r << CHUNK_BITS)] = x[r];
}

// first variant: reads separate re/im arrays, writes interleaved float2
__global__ void __launch_bounds__(PH_THREADS)
k_pass_high_first(const float* __restrict__ sre,
                  const float* __restrict__ sim,
                  float2* __restrict__ out) {
    int gid = blockIdx.x * blockDim.x + threadIdx.x;
    int b = gid >> CHUNK_BITS;
    int u = gid & (CHUNK - 1);
    long base = (long)b * DIM + u;

    float2 x[16];
#pragma unroll
    for (int r = 0; r < 16; ++r) {
        long idx = base + ((long)r << CHUNK_BITS);
        x[r] = make_float2(sre[idx], sim[idx]);
    }
#pragma unroll
    for (int w = 0; w < 4; ++w) {
        float4 g = g_gates[w];               // layer 0
        int m = 8 >> w;
#pragma unroll
        for (int r = 0; r < 16; ++r)
            if (!(r & m)) apply_gate(x[r], x[r | m], g);
    }
#pragma unroll
    for (int r = 0; r < 16; ++r) out[base + ((long)r << CHUNK_BITS)] = x[r];
}

// ---------------------------------------------------------------------------
// pass_low: gates on wires 4..17 (bits 13..0) in shared memory, then the
// CNOT-ladder permutation (inverse-Gray scatter) on the write.
// Four micro-stages of 4/4/3/3 bits keep at most 16 float2 (32 regs) live
// per thread -> no register spills at 512 threads.
// last==true: skip state write, compute <Z_w> partials instead.
// ---------------------------------------------------------------------------
__global__ void __launch_bounds__(PL_THREADS, 1)
k_pass_low(const float2* __restrict__ in,
           float2* __restrict__ out,
           int layer, int last) {
    extern __shared__ float2 sh[];           // 2^14 float2 = 128KB
    int tid = threadIdx.x;
    int b = blockIdx.x >> 4;
    int C = blockIdx.x & 15;                 // source chunk (bits 14..17)
    const float2* src = in + (long)b * DIM + ((long)C << CHUNK_BITS);
    const float4* gt = &g_gates[layer * NUM_WIRES];

    for (int t = tid; t < CHUNK; t += PL_THREADS) sh[SW(t)] = src[t];
    __syncthreads();

    // stage 1: bits 0..3 (wires 17..14). 1024 groups of 16, 2 per thread.
    #pragma unroll
    for (int i = 0; i < 2; ++i) {
        int g4 = tid + i * PL_THREADS;       // group id = bits 4..13
        int base = g4 << 4;
        float2 x[16];
#pragma unroll
        for (int j = 0; j < 16; ++j) x[j] = sh[SW(base + j)];
#pragma unroll
        for (int p = 0; p < 4; ++p) {
            float4 g = gt[17 - p];
            int m = 1 << p;
#pragma unroll
            for (int j = 0; j < 16; ++j)
                if (!(j & m)) apply_gate(x[j], x[j | m], g);
        }
#pragma unroll
        for (int j = 0; j < 16; ++j) sh[SW(base + j)] = x[j];
    }
    __syncthreads();

    // stage 2: bits 4..7 (wires 13..10). group = bits 0..3 x bits 8..13.
    #pragma unroll
    for (int i = 0; i < 2; ++i) {
        int g4 = tid + i * PL_THREADS;
        int low4 = g4 & 15;
        int hi   = g4 >> 4;                  // bits 8..13 (64 values)
        int base = low4 | (hi << 8);
        float2 x[16];
#pragma unroll
        for (int j = 0; j < 16; ++j) x[j] = sh[SW(base | (j << 4))];
#pragma unroll
        for (int p = 0; p < 4; ++p) {
            float4 g = gt[13 - p];
            int m = 1 << p;
#pragma unroll
            for (int j = 0; j < 16; ++j)
                if (!(j & m)) apply_gate(x[j], x[j | m], g);
        }
#pragma unroll
        for (int j = 0; j < 16; ++j) sh[SW(base | (j << 4))] = x[j];
    }
    __syncthreads();

    // stage 3: bits 8..10 (wires 9..7). group = bits 0..7 x bits 11..13.
    #pragma unroll
    for (int i = 0; i < 4; ++i) {
        int g3 = tid + i * PL_THREADS;       // 2048 groups
        int low8 = g3 & 255;
        int hi   = g3 >> 8;                  // bits 11..13 (8 values)
        int base = low8 | (hi << 11);
        float2 x[8];
#pragma unroll
        for (int j = 0; j < 8; ++j) x[j] = sh[SW(base | (j << 8))];
#pragma unroll
        for (int p = 0; p < 3; ++p) {
            float4 g = gt[9 - p];
            int m = 1 << p;
#pragma unroll
            for (int j = 0; j < 8; ++j)
                if (!(j & m)) apply_gate(x[j], x[j | m], g);
        }
#pragma unroll
        for (int j = 0; j < 8; ++j) sh[SW(base | (j << 8))] = x[j];
    }
    __syncthreads();

    // stage 4: bits 11..13 (wires 6..4). group = bits 0..10.
    #pragma unroll
    for (int i = 0; i < 4; ++i) {
        int g3 = tid + i * PL_THREADS;       // 2048 groups (bits 0..10)
        float2 x[8];
#pragma unroll
        for (int j = 0; j < 8; ++j) x[j] = sh[SW(g3 | (j << 11))];
#pragma unroll
        for (int p = 0; p < 3; ++p) {
            float4 g = gt[6 - p];
            int m = 1 << p;
#pragma unroll
            for (int j = 0; j < 8; ++j)
                if (!(j & m)) apply_gate(x[j], x[j | m], g);
        }
#pragma unroll
        for (int j = 0; j < 8; ++j) sh[SW(g3 | (j << 11))] = x[j];
    }
    __syncthreads();

    // CNOT-ladder permutation: dest = invgray18(src index)
    int pm = (__popc(C) & 1) ? (CHUNK - 1) : 0;
    int Cd = C; Cd ^= Cd >> 1; Cd ^= Cd >> 2;       // invgray4

    if (!last) {
        float2* dst = out + (long)b * DIM + ((long)Cd << CHUNK_BITS);
        for (int t = tid; t < CHUNK; t += PL_THREADS) {
            int d = invgray(t) ^ pm;
            dst[d] = sh[SW(t)];
        }
    } else {
        float acc[NUM_WIRES];
#pragma unroll
        for (int w = 0; w < NUM_WIRES; ++w) acc[w] = 0.0f;
        int hi = Cd << CHUNK_BITS;
        for (int t = tid; t < CHUNK; t += PL_THREADS) {
            float2 v = sh[SW(t)];
            float pr = v.x * v.x + v.y * v.y;
            int d = hi | (invgray(t) ^ pm);          // full 18-bit dest index
            unsigned pbits = __float_as_uint(pr);
#pragma unroll
            for (int w = 0; w < NUM_WIRES; ++w) {
                unsigned bit = (unsigned)(d >> (17 - w)) & 1u;
                acc[w] += __uint_as_float(pbits ^ (bit << 31));  // +pr / -pr
            }
        }
        // warp reduction
#pragma unroll
        for (int w = 0; w < NUM_WIRES; ++w)
#pragma unroll
            for (int o = 16; o; o >>= 1)
                acc[w] += __shfl_down_sync(0xFFFFFFFFu, acc[w], o);
        __syncthreads();                      // all sh reads above are done
        float* scratch = (float*)sh;          // reuse: 16 warps x 18
        int warp = tid >> 5, lane = tid & 31;
        if (lane == 0)
#pragma unroll
            for (int w = 0; w < NUM_WIRES; ++w) scratch[warp * NUM_WIRES + w] = acc[w];
        __syncthreads();
        if (tid < NUM_WIRES) {
            float s = 0.0f;
#pragma unroll
            for (int k = 0; k < PL_THREADS / 32; ++k) s += scratch[k * NUM_WIRES + tid];
            g_partial[(b * NCHUNK + C) * NUM_WIRES + tid] = s;
        }
    }
}

// ---------------------------------------------------------------------------
// head: feats @ head_w.T + head_b
// ---------------------------------------------------------------------------
__global__ void k_head(const float* __restrict__ head_w,
                       const float* __restrict__ head_b,
                       float* __restrict__ out) {
    int b = threadIdx.x;
    if (b < BATCH) {
        float s = head_b[0];
#pragma unroll
        for (int w = 0; w < NUM_WIRES; ++w) {
            float f = 0.0f;
#pragma unroll
            for (int c = 0; c < NCHUNK; ++c)
                f += g_partial[(b * NCHUNK + c) * NUM_WIRES + w];
            s = fmaf(f, head_w[w], s);
        }
        out[b] = s;
    }
}

// ---------------------------------------------------------------------------
extern "C" void kernel_launch(void* const* d_in, const int* in_sizes, int n_in,
                              void* d_out, int out_size) {
    const float* state_re = (const float*)d_in[0];
    const float* state_im = (const float*)d_in[1];
    const float* params   = (const float*)d_in[2];
    const float* head_w   = (const float*)d_in[3];
    const float* head_b   = (const float*)d_in[4];
    float* out = (float*)d_out;

    // 128KB dynamic shared for pass_low (idempotent; not a stream op)
    cudaFuncSetAttribute(k_pass_low, cudaFuncAttributeMaxDynamicSharedMemorySize,
                         CHUNK * (int)sizeof(float2));

    const int ph_blocks = (BATCH * CHUNK) / PH_THREADS;   // 4096
    const int pl_blocks = BATCH * NCHUNK;                 // 1024
    const int shmem = CHUNK * (int)sizeof(float2);        // 128KB

    k_prep<<<1, 64>>>(params);

    // layer 0
    k_pass_high_first<<<ph_blocks, PH_THREADS>>>(state_re, state_im, g_buf0);
    k_pass_low<<<pl_blocks, PL_THREADS, shmem>>>(g_buf0, g_buf1, 0, 0);
    // layer 1
    k_pass_high<<<ph_blocks, PH_THREADS>>>(g_buf1, 1);
    k_pass_low<<<pl_blocks, PL_THREADS, shmem>>>(g_buf1, g_buf0, 1, 0);
    // layer 2
    k_pass_high<<<ph_blocks, PH_THREADS>>>(g_buf0, 2);
    k_pass_low<<<pl_blocks, PL_THREADS, shmem>>>(g_buf0, g_buf1, 2, 1);  // expvals only

    k_head<<<1, 64>>>(head_w, head_b, out);
}

// round 3
// speedup vs baseline: 1.1537x; 1.1537x over previous
#include <cuda_runtime.h>
#include <math.h>

#define NUM_WIRES 18
#define BATCH     64
#define DIM       262144            // 2^18
#define CHUNK_BITS 14
#define CHUNK     16384             // 2^14
#define NCHUNK    16                // 2^(18-14)
#define PL_THREADS 512
#define PH_THREADS 256

// Ping-pong state buffers. __device__ globals are the sanctioned scratch.
__device__ float2 g_buf0[BATCH * DIM];
__device__ float2 g_buf1[BATCH * DIM];
// Expval partials: [batch][chunk][wire]
__device__ float g_partial[BATCH * NCHUNK * NUM_WIRES];

// ---------------------------------------------------------------------------
// helpers
// ---------------------------------------------------------------------------

// Apply fused RZ(tz)*RY(ty) to amplitude pair (a = bit0 branch, b = bit1 branch)
__device__ __forceinline__ void apply_gate(float2& a, float2& b, float4 g) {
    float ar = fmaf(g.x, a.x, -g.y * b.x);
    float ai = fmaf(g.x, a.y, -g.y * b.y);
    float br = fmaf(g.y, a.x,  g.x * b.x);
    float bi = fmaf(g.y, a.y,  g.x * b.y);
    a.x = fmaf(g.z, ar,  g.w * ai);
    a.y = fmaf(g.z, ai, -g.w * ar);
    b.x = fmaf(g.z, br, -g.w * bi);
    b.y = fmaf(g.z, bi,  g.w * br);
}

// same gate applied to two complex amplitudes packed in float4 (x,y)+(z,w)
__device__ __forceinline__ void apply_gate4(float4& a, float4& b, float4 g) {
    float ar, ai, br, bi;
    ar = fmaf(g.x, a.x, -g.y * b.x);  ai = fmaf(g.x, a.y, -g.y * b.y);
    br = fmaf(g.y, a.x,  g.x * b.x);  bi = fmaf(g.y, a.y,  g.x * b.y);
    a.x = fmaf(g.z, ar,  g.w * ai);   a.y = fmaf(g.z, ai, -g.w * ar);
    b.x = fmaf(g.z, br, -g.w * bi);   b.y = fmaf(g.z, bi,  g.w * br);
    ar = fmaf(g.x, a.z, -g.y * b.z);  ai = fmaf(g.x, a.w, -g.y * b.w);
    br = fmaf(g.y, a.z,  g.x * b.z);  bi = fmaf(g.y, a.w,  g.x * b.w);
    a.z = fmaf(g.z, ar,  g.w * ai);   a.w = fmaf(g.z, ai, -g.w * ar);
    b.z = fmaf(g.z, br, -g.w * bi);   b.w = fmaf(g.z, bi,  g.w * br);
}

// shared-memory XOR swizzle (kills bank conflicts for all stage patterns)
__device__ __forceinline__ int SW(int t) { return t ^ ((t >> 5) & 31); }

// inverse Gray code (prefix-xor from MSB) for values < 2^16
__device__ __forceinline__ int invgray(int t) {
    t ^= t >> 1; t ^= t >> 2; t ^= t >> 4; t ^= t >> 8;
    return t;
}

// compute this layer's 18 gate coefficient quads into shared memory
__device__ __forceinline__ void load_gates(float4* sg, const float* params,
                                           int layer, int tid) {
    if (tid < NUM_WIRES) {
        float ty = params[(layer * 2 + 0) * NUM_WIRES + tid] * 0.5f;
        float tz = params[(layer * 2 + 1) * NUM_WIRES + tid] * 0.5f;
        float cy, sy, cz, sz;
        __sincosf(0.0f, &sy, &cy);   // dummy to keep fast path consistent
        cy = cosf(ty); sy = sinf(ty);
        cz = cosf(tz); sz = sinf(tz);
        sg[tid] = make_float4(cy, sy, cz, sz);
    }
}

// ---------------------------------------------------------------------------
// pass_high: gates on wires 0..3 (index bits 17..14). Register-only, in-place.
// Each thread owns 16 amplitude PAIRS (float4) strided by 2^14 complex.
// ---------------------------------------------------------------------------
__global__ void __launch_bounds__(PH_THREADS)
k_pass_high(float2* __restrict__ buf, const float* __restrict__ params, int layer) {
    __shared__ float4 sg[NUM_WIRES];
    load_gates(sg, params, layer, threadIdx.x);
    __syncthreads();

    int gid = blockIdx.x * blockDim.x + threadIdx.x;   // BATCH * CHUNK/2 threads
    int b = gid >> (CHUNK_BITS - 1);
    int u2 = gid & (CHUNK / 2 - 1);
    float4* p = (float4*)(buf + (long)b * DIM + 2 * u2);

    float4 x[16];
#pragma unroll
    for (int r = 0; r < 16; ++r) x[r] = p[(long)r << (CHUNK_BITS - 1)];

#pragma unroll
    for (int w = 0; w < 4; ++w) {
        float4 g = sg[w];
        int m = 8 >> w;
#pragma unroll
        for (int r = 0; r < 16; ++r)
            if (!(r & m)) apply_gate4(x[r], x[r | m], g);
    }

#pragma unroll
    for (int r = 0; r < 16; ++r) p[(long)r << (CHUNK_BITS - 1)] = x[r];
}

// first variant: reads separate re/im arrays (float2 each), writes interleaved
__global__ void __launch_bounds__(PH_THREADS)
k_pass_high_first(const float* __restrict__ sre,
                  const float* __restrict__ sim,
                  float2* __restrict__ out,
                  const float* __restrict__ params) {
    __shared__ float4 sg[NUM_WIRES];
    load_gates(sg, params, 0, threadIdx.x);
    __syncthreads();

    int gid = blockIdx.x * blockDim.x + threadIdx.x;
    int b = gid >> (CHUNK_BITS - 1);
    int u2 = gid & (CHUNK / 2 - 1);
    long base = (long)b * DIM + 2 * u2;

    float4 x[16];
#pragma unroll
    for (int r = 0; r < 16; ++r) {
        long idx = base + ((long)r << CHUNK_BITS);
        float2 re = *(const float2*)(sre + idx);
        float2 im = *(const float2*)(sim + idx);
        x[r] = make_float4(re.x, im.x, re.y, im.y);
    }
#pragma unroll
    for (int w = 0; w < 4; ++w) {
        float4 g = sg[w];
        int m = 8 >> w;
#pragma unroll
        for (int r = 0; r < 16; ++r)
            if (!(r & m)) apply_gate4(x[r], x[r | m], g);
    }
    float4* p = (float4*)(out + base);
#pragma unroll
    for (int r = 0; r < 16; ++r) p[(long)r << (CHUNK_BITS - 1)] = x[r];
}

// ---------------------------------------------------------------------------
// pass_low: gates on wires 4..17 (bits 13..0) in shared memory, then the
// CNOT-ladder permutation (inverse-Gray scatter, float4-pair stores).
// last==true: skip state write, compute <Z_w> partials instead.
// ---------------------------------------------------------------------------
__global__ void __launch_bounds__(PL_THREADS, 1)
k_pass_low(const float2* __restrict__ in,
           float2* __restrict__ out,
           const float* __restrict__ params,
           int layer, int last) {
    extern __shared__ float2 sh[];           // 2^14 float2 = 128KB
    __shared__ float4 sg[NUM_WIRES];
    int tid = threadIdx.x;
    load_gates(sg, params, layer, tid);

    int b = blockIdx.x >> 4;
    int C = blockIdx.x & 15;                 // source chunk (bits 14..17)
    const float4* src4 = (const float4*)(in + (long)b * DIM + ((long)C << CHUNK_BITS));

    for (int t4 = tid; t4 < CHUNK / 2; t4 += PL_THREADS) {
        float4 v = src4[t4];
        sh[SW(2 * t4)]     = make_float2(v.x, v.y);
        sh[SW(2 * t4 + 1)] = make_float2(v.z, v.w);
    }
    __syncthreads();

    // stage 1: bits 0..3 (wires 17..14). 1024 groups of 16, 2 per thread.
    #pragma unroll
    for (int i = 0; i < 2; ++i) {
        int g4 = tid + i * PL_THREADS;
        int base = g4 << 4;
        float2 x[16];
#pragma unroll
        for (int j = 0; j < 16; ++j) x[j] = sh[SW(base + j)];
#pragma unroll
        for (int p = 0; p < 4; ++p) {
            float4 g = sg[17 - p];
            int m = 1 << p;
#pragma unroll
            for (int j = 0; j < 16; ++j)
                if (!(j & m)) apply_gate(x[j], x[j | m], g);
        }
#pragma unroll
        for (int j = 0; j < 16; ++j) sh[SW(base + j)] = x[j];
    }
    __syncthreads();

    // stage 2: bits 4..7 (wires 13..10)
    #pragma unroll
    for (int i = 0; i < 2; ++i) {
        int g4 = tid + i * PL_THREADS;
        int low4 = g4 & 15;
        int hi   = g4 >> 4;
        int base = low4 | (hi << 8);
        float2 x[16];
#pragma unroll
        for (int j = 0; j < 16; ++j) x[j] = sh[SW(base | (j << 4))];
#pragma unroll
        for (int p = 0; p < 4; ++p) {
            float4 g = sg[13 - p];
            int m = 1 << p;
#pragma unroll
            for (int j = 0; j < 16; ++j)
                if (!(j & m)) apply_gate(x[j], x[j | m], g);
        }
#pragma unroll
        for (int j = 0; j < 16; ++j) sh[SW(base | (j << 4))] = x[j];
    }
    __syncthreads();

    // stage 3: bits 8..10 (wires 9..7)
    #pragma unroll
    for (int i = 0; i < 4; ++i) {
        int g3 = tid + i * PL_THREADS;
        int low8 = g3 & 255;
        int hi   = g3 >> 8;
        int base = low8 | (hi << 11);
        float2 x[8];
#pragma unroll
        for (int j = 0; j < 8; ++j) x[j] = sh[SW(base | (j << 8))];
#pragma unroll
        for (int p = 0; p < 3; ++p) {
            float4 g = sg[9 - p];
            int m = 1 << p;
#pragma unroll
            for (int j = 0; j < 8; ++j)
                if (!(j & m)) apply_gate(x[j], x[j | m], g);
        }
#pragma unroll
        for (int j = 0; j < 8; ++j) sh[SW(base | (j << 8))] = x[j];
    }
    __syncthreads();

    // stage 4: bits 11..13 (wires 6..4)
    #pragma unroll
    for (int i = 0; i < 4; ++i) {
        int g3 = tid + i * PL_THREADS;
        float2 x[8];
#pragma unroll
        for (int j = 0; j < 8; ++j) x[j] = sh[SW(g3 | (j << 11))];
#pragma unroll
        for (int p = 0; p < 3; ++p) {
            float4 g = sg[6 - p];
            int m = 1 << p;
#pragma unroll
            for (int j = 0; j < 8; ++j)
                if (!(j & m)) apply_gate(x[j], x[j | m], g);
        }
#pragma unroll
        for (int j = 0; j < 8; ++j) sh[SW(g3 | (j << 11))] = x[j];
    }
    __syncthreads();

    // CNOT-ladder permutation: dest = invgray18(src index)
    int pm = (__popc(C) & 1) ? (CHUNK - 1) : 0;
    int Cd = C; Cd ^= Cd >> 1; Cd ^= Cd >> 2;       // invgray4

    if (!last) {
        // invgray maps the pair {t, t+1} (t even) to {q, q^1}: 16B stores stay legal
        float4* dst4 = (float4*)(out + (long)b * DIM + ((long)Cd << CHUNK_BITS));
        for (int t4 = tid; t4 < CHUNK / 2; t4 += PL_THREADS) {
            int t = 2 * t4;
            int q = invgray(t) ^ pm;
            float2 v0 = sh[SW(t)];
            float2 v1 = sh[SW(t + 1)];
            float4 o = (q & 1) ? make_float4(v1.x, v1.y, v0.x, v0.y)
                               : make_float4(v0.x, v0.y, v1.x, v1.y);
            dst4[q >> 1] = o;
        }
    } else {
        float acc[NUM_WIRES];
#pragma unroll
        for (int w = 0; w < NUM_WIRES; ++w) acc[w] = 0.0f;
        int hi = Cd << CHUNK_BITS;
        for (int t4 = tid; t4 < CHUNK / 2; t4 += PL_THREADS) {
            int t = 2 * t4;
            float2 v0 = sh[SW(t)];
            float2 v1 = sh[SW(t + 1)];
            float pr0 = v0.x * v0.x + v0.y * v0.y;
            float pr1 = v1.x * v1.x + v1.y * v1.y;
            int q = invgray(t) ^ pm;                  // dest low bits for t (even)
            int d = hi | q;                           // d and d^1 are the pair
            // wires 0..16 see the same bits for both pair members (they differ
            // only in bit0 = wire 17)
            float both = pr0 + pr1;
            unsigned bb = __float_as_uint(both);
#pragma unroll
            for (int w = 0; w < 17; ++w) {
                unsigned bit = (unsigned)(d >> (17 - w)) & 1u;
                acc[w] += __uint_as_float(bb ^ (bit << 31));
            }
            // wire 17: sign from bit0; member with bit0=0 positive
            float diff = pr0 - pr1;                   // d even: pr0 at bit0=0
            acc[17] += (q & 1) ? -diff : diff;
        }
        // warp reduction
#pragma unroll
        for (int w = 0; w < NUM_WIRES; ++w)
#pragma unroll
            for (int o = 16; o; o >>= 1)
                acc[w] += __shfl_down_sync(0xFFFFFFFFu, acc[w], o);
        __syncthreads();
        float* scratch = (float*)sh;
        int warp = tid >> 5, lane = tid & 31;
        if (lane == 0)
#pragma unroll
            for (int w = 0; w < NUM_WIRES; ++w) scratch[warp * NUM_WIRES + w] = acc[w];
        __syncthreads();
        if (tid < NUM_WIRES) {
            float s = 0.0f;
#pragma unroll
            for (int k = 0; k < PL_THREADS / 32; ++k) s += scratch[k * NUM_WIRES + tid];
            g_partial[(b * NCHUNK + C) * NUM_WIRES + tid] = s;
        }
    }
}

// ---------------------------------------------------------------------------
// head: feats @ head_w.T + head_b
// ---------------------------------------------------------------------------
__global__ void k_head(const float* __restrict__ head_w,
                       const float* __restrict__ head_b,
                       float* __restrict__ out) {
    int b = threadIdx.x;
    if (b < BATCH) {
        float s = head_b[0];
#pragma unroll
        for (int w = 0; w < NUM_WIRES; ++w) {
            float f = 0.0f;
#pragma unroll
            for (int c = 0; c < NCHUNK; ++c)
                f += g_partial[(b * NCHUNK + c) * NUM_WIRES + w];
            s = fmaf(f, head_w[w], s);
        }
        out[b] = s;
    }
}

// ---------------------------------------------------------------------------
extern "C" void kernel_launch(void* const* d_in, const int* in_sizes, int n_in,
                              void* d_out, int out_size) {
    const float* state_re = (const float*)d_in[0];
    const float* state_im = (const float*)d_in[1];
    const float* params   = (const float*)d_in[2];
    const float* head_w   = (const float*)d_in[3];
    const float* head_b   = (const float*)d_in[4];
    float* out = (float*)d_out;

    cudaFuncSetAttribute(k_pass_low, cudaFuncAttributeMaxDynamicSharedMemorySize,
                         CHUNK * (int)sizeof(float2));

    const int ph_blocks = (BATCH * CHUNK / 2) / PH_THREADS;   // 2048
    const int pl_blocks = BATCH * NCHUNK;                     // 1024
    const int shmem = CHUNK * (int)sizeof(float2);            // 128KB

    // layer 0
    k_pass_high_first<<<ph_blocks, PH_THREADS>>>(state_re, state_im, g_buf0, params);
    k_pass_low<<<pl_blocks, PL_THREADS, shmem>>>(g_buf0, g_buf1, params, 0, 0);
    // layer 1
    k_pass_high<<<ph_blocks, PH_THREADS>>>(g_buf1, params, 1);
    k_pass_low<<<pl_blocks, PL_THREADS, shmem>>>(g_buf1, g_buf0, params, 1, 0);
    // layer 2
    k_pass_high<<<ph_blocks, PH_THREADS>>>(g_buf0, params, 2);
    k_pass_low<<<pl_blocks, PL_THREADS, shmem>>>(g_buf0, g_buf1, params, 2, 1);

    k_head<<<1, 64>>>(head_w, head_b, out);
}

// round 4
// speedup vs baseline: 1.1690x; 1.0133x over previous
#include <cuda_runtime.h>
#include <math.h>

#define NUM_WIRES 18
#define BATCH     64
#define DIM       262144            // 2^18
#define CHUNK_BITS 14
#define CHUNK     16384             // 2^14
#define NCHUNK    16                // 2^(18-14)
#define PL_THREADS 512
#define PH_THREADS 256

// Ping-pong state buffers. __device__ globals are the sanctioned scratch.
__device__ float2 g_buf0[BATCH * DIM];
__device__ float2 g_buf1[BATCH * DIM];
// Expval partials: [batch][chunk][wire]
__device__ float g_partial[BATCH * NCHUNK * NUM_WIRES];

// ---------------------------------------------------------------------------
// helpers
// ---------------------------------------------------------------------------

// Apply fused RZ(tz)*RY(ty) to amplitude pair (a = bit0 branch, b = bit1 branch)
__device__ __forceinline__ void apply_gate(float2& a, float2& b, float4 g) {
    float ar = fmaf(g.x, a.x, -g.y * b.x);
    float ai = fmaf(g.x, a.y, -g.y * b.y);
    float br = fmaf(g.y, a.x,  g.x * b.x);
    float bi = fmaf(g.y, a.y,  g.x * b.y);
    a.x = fmaf(g.z, ar,  g.w * ai);
    a.y = fmaf(g.z, ai, -g.w * ar);
    b.x = fmaf(g.z, br, -g.w * bi);
    b.y = fmaf(g.z, bi,  g.w * br);
}

// shared-memory XOR swizzle: conflict-free (half-warp-distinct bank pairs) for
// fill, all 4 gate stages, scatter and expval access patterns. Bijective.
__device__ __forceinline__ int SW(int t) { return t ^ ((t >> 4) & 63); }

// inverse Gray code (prefix-xor from MSB) for values < 2^16
__device__ __forceinline__ int invgray(int t) {
    t ^= t >> 1; t ^= t >> 2; t ^= t >> 4; t ^= t >> 8;
    return t;
}

// compute this layer's gate coefficient quads into shared memory
__device__ __forceinline__ void load_gates(float4* sg, const float* params,
                                           int layer, int tid) {
    if (tid < NUM_WIRES) {
        float ty = params[(layer * 2 + 0) * NUM_WIRES + tid] * 0.5f;
        float tz = params[(layer * 2 + 1) * NUM_WIRES + tid] * 0.5f;
        sg[tid] = make_float4(cosf(ty), sinf(ty), cosf(tz), sinf(tz));
    }
}

// ---------------------------------------------------------------------------
// pass_high: gates on wires 0..3 (index bits 17..14). Register-only, in-place.
// One float2 amplitude x16 per thread, strided 2^14; all 16 loads batched
// before any compute (MLP=16). <=64 regs, 4 CTAs/SM.
// ---------------------------------------------------------------------------
__global__ void __launch_bounds__(PH_THREADS, 4)
k_pass_high(float2* __restrict__ buf, const float* __restrict__ params, int layer) {
    __shared__ float4 sg[NUM_WIRES];
    load_gates(sg, params, layer, threadIdx.x);
    __syncthreads();

    int gid = blockIdx.x * PH_THREADS + threadIdx.x;   // BATCH*CHUNK threads
    int b = gid >> CHUNK_BITS;
    int u = gid & (CHUNK - 1);
    float2* p = buf + (long)b * DIM + u;

    float2 x[16];
#pragma unroll
    for (int r = 0; r < 16; ++r) x[r] = p[(long)r << CHUNK_BITS];

#pragma unroll
    for (int w = 0; w < 4; ++w) {
        float4 g = sg[w];
        int m = 8 >> w;
#pragma unroll
        for (int r = 0; r < 16; ++r)
            if (!(r & m)) apply_gate(x[r], x[r | m], g);
    }

#pragma unroll
    for (int r = 0; r < 16; ++r) p[(long)r << CHUNK_BITS] = x[r];
}

// first variant: reads separate re/im arrays, writes interleaved float2
__global__ void __launch_bounds__(PH_THREADS, 4)
k_pass_high_first(const float* __restrict__ sre,
                  const float* __restrict__ sim,
                  float2* __restrict__ out,
                  const float* __restrict__ params) {
    __shared__ float4 sg[NUM_WIRES];
    load_gates(sg, params, 0, threadIdx.x);
    __syncthreads();

    int gid = blockIdx.x * PH_THREADS + threadIdx.x;
    int b = gid >> CHUNK_BITS;
    int u = gid & (CHUNK - 1);
    long base = (long)b * DIM + u;

    float re[16], im[16];
#pragma unroll
    for (int r = 0; r < 16; ++r) re[r] = sre[base + ((long)r << CHUNK_BITS)];
#pragma unroll
    for (int r = 0; r < 16; ++r) im[r] = sim[base + ((long)r << CHUNK_BITS)];

    float2 x[16];
#pragma unroll
    for (int r = 0; r < 16; ++r) x[r] = make_float2(re[r], im[r]);

#pragma unroll
    for (int w = 0; w < 4; ++w) {
        float4 g = sg[w];
        int m = 8 >> w;
#pragma unroll
        for (int r = 0; r < 16; ++r)
            if (!(r & m)) apply_gate(x[r], x[r | m], g);
    }
    float2* p = out + base;
#pragma unroll
    for (int r = 0; r < 16; ++r) p[(long)r << CHUNK_BITS] = x[r];
}

// ---------------------------------------------------------------------------
// pass_low: gates on wires 4..17 (bits 13..0) in shared memory, then the
// CNOT-ladder permutation (inverse-Gray scatter, float4-pair global stores).
// Fill is 16 explicitly batched LDG.128 (MLP=16). <=128 regs, 1 CTA/SM.
// last==true: skip state write, compute <Z_w> partials instead.
// ---------------------------------------------------------------------------
__global__ void __launch_bounds__(PL_THREADS, 1)
k_pass_low(const float2* __restrict__ in,
           float2* __restrict__ out,
           const float* __restrict__ params,
           int layer, int last) {
    extern __shared__ float2 sh[];           // 2^14 float2 = 128KB
    __shared__ float4 sg[NUM_WIRES];
    int tid = threadIdx.x;
    load_gates(sg, params, layer, tid);

    int b = blockIdx.x >> 4;
    int C = blockIdx.x & 15;                 // source chunk (bits 14..17)
    const float4* src4 = (const float4*)(in + (long)b * DIM + ((long)C << CHUNK_BITS));

    // batched fill: 16 independent 16B loads, then smem stores
    {
        float4 v[16];
#pragma unroll
        for (int k = 0; k < 16; ++k) v[k] = src4[tid + k * PL_THREADS];
#pragma unroll
        for (int k = 0; k < 16; ++k) {
            int t = 2 * (tid + k * PL_THREADS);
            sh[SW(t)]     = make_float2(v[k].x, v[k].y);
            sh[SW(t + 1)] = make_float2(v[k].z, v[k].w);
        }
    }
    __syncthreads();

    // stage 1: bits 0..3 (wires 17..14). 1024 groups of 16, 2 per thread.
    #pragma unroll
    for (int i = 0; i < 2; ++i) {
        int g4 = tid + i * PL_THREADS;
        int base = g4 << 4;
        float2 x[16];
#pragma unroll
        for (int j = 0; j < 16; ++j) x[j] = sh[SW(base + j)];
#pragma unroll
        for (int p = 0; p < 4; ++p) {
            float4 g = sg[17 - p];
            int m = 1 << p;
#pragma unroll
            for (int j = 0; j < 16; ++j)
                if (!(j & m)) apply_gate(x[j], x[j | m], g);
        }
#pragma unroll
        for (int j = 0; j < 16; ++j) sh[SW(base + j)] = x[j];
    }
    __syncthreads();

    // stage 2: bits 4..7 (wires 13..10)
    #pragma unroll
    for (int i = 0; i < 2; ++i) {
        int g4 = tid + i * PL_THREADS;
        int low4 = g4 & 15;
        int hi   = g4 >> 4;
        int base = low4 | (hi << 8);
        float2 x[16];
#pragma unroll
        for (int j = 0; j < 16; ++j) x[j] = sh[SW(base | (j << 4))];
#pragma unroll
        for (int p = 0; p < 4; ++p) {
            float4 g = sg[13 - p];
            int m = 1 << p;
#pragma unroll
            for (int j = 0; j < 16; ++j)
                if (!(j & m)) apply_gate(x[j], x[j | m], g);
        }
#pragma unroll
        for (int j = 0; j < 16; ++j) sh[SW(base | (j << 4))] = x[j];
    }
    __syncthreads();

    // stage 3: bits 8..10 (wires 9..7)
    #pragma unroll
    for (int i = 0; i < 4; ++i) {
        int g3 = tid + i * PL_THREADS;
        int low8 = g3 & 255;
        int hi   = g3 >> 8;
        int base = low8 | (hi << 11);
        float2 x[8];
#pragma unroll
        for (int j = 0; j < 8; ++j) x[j] = sh[SW(base | (j << 8))];
#pragma unroll
        for (int p = 0; p < 3; ++p) {
            float4 g = sg[9 - p];
            int m = 1 << p;
#pragma unroll
            for (int j = 0; j < 8; ++j)
                if (!(j & m)) apply_gate(x[j], x[j | m], g);
        }
#pragma unroll
        for (int j = 0; j < 8; ++j) sh[SW(base | (j << 8))] = x[j];
    }
    __syncthreads();

    // stage 4: bits 11..13 (wires 6..4)
    #pragma unroll
    for (int i = 0; i < 4; ++i) {
        int g3 = tid + i * PL_THREADS;
        float2 x[8];
#pragma unroll
        for (int j = 0; j < 8; ++j) x[j] = sh[SW(g3 | (j << 11))];
#pragma unroll
        for (int p = 0; p < 3; ++p) {
            float4 g = sg[6 - p];
            int m = 1 << p;
#pragma unroll
            for (int j = 0; j < 8; ++j)
                if (!(j & m)) apply_gate(x[j], x[j | m], g);
        }
#pragma unroll
        for (int j = 0; j < 8; ++j) sh[SW(g3 | (j << 11))] = x[j];
    }
    __syncthreads();

    // CNOT-ladder permutation: dest = invgray18(src index)
    int pm = (__popc(C) & 1) ? (CHUNK - 1) : 0;
    int Cd = C; Cd ^= Cd >> 1; Cd ^= Cd >> 2;       // invgray4

    if (!last) {
        // invgray maps pair {t,t+1} (t even) to {q, q^1}: 16B stores stay legal
        float4* dst4 = (float4*)(out + (long)b * DIM + ((long)Cd << CHUNK_BITS));
#pragma unroll
        for (int k = 0; k < 16; ++k) {
            int t = 2 * (tid + k * PL_THREADS);
            int q = invgray(t) ^ pm;
            float2 v0 = sh[SW(t)];
            float2 v1 = sh[SW(t + 1)];
            float4 o = (q & 1) ? make_float4(v1.x, v1.y, v0.x, v0.y)
                               : make_float4(v0.x, v0.y, v1.x, v1.y);
            dst4[q >> 1] = o;
        }
    } else {
        float acc[NUM_WIRES];
#pragma unroll
        for (int w = 0; w < NUM_WIRES; ++w) acc[w] = 0.0f;
        int hi = Cd << CHUNK_BITS;
#pragma unroll
        for (int k = 0; k < 16; ++k) {
            int t = 2 * (tid + k * PL_THREADS);
            float2 v0 = sh[SW(t)];
            float2 v1 = sh[SW(t + 1)];
            float pr0 = v0.x * v0.x + v0.y * v0.y;
            float pr1 = v1.x * v1.x + v1.y * v1.y;
            int q = invgray(t) ^ pm;
            int d = hi | q;
            float both = pr0 + pr1;
            unsigned bb = __float_as_uint(both);
#pragma unroll
            for (int w = 0; w < 17; ++w) {
                unsigned bit = (unsigned)(d >> (17 - w)) & 1u;
                acc[w] += __uint_as_float(bb ^ (bit << 31));
            }
            float diff = pr0 - pr1;
            acc[17] += (q & 1) ? -diff : diff;
        }
#pragma unroll
        for (int w = 0; w < NUM_WIRES; ++w)
#pragma unroll
            for (int o = 16; o; o >>= 1)
                acc[w] += __shfl_down_sync(0xFFFFFFFFu, acc[w], o);
        __syncthreads();
        float* scratch = (float*)sh;
        int warp = tid >> 5, lane = tid & 31;
        if (lane == 0)
#pragma unroll
            for (int w = 0; w < NUM_WIRES; ++w) scratch[warp * NUM_WIRES + w] = acc[w];
        __syncthreads();
        if (tid < NUM_WIRES) {
            float s = 0.0f;
#pragma unroll
            for (int k = 0; k < PL_THREADS / 32; ++k) s += scratch[k * NUM_WIRES + tid];
            g_partial[(b * NCHUNK + C) * NUM_WIRES + tid] = s;
        }
    }
}

// ---------------------------------------------------------------------------
// head: feats @ head_w.T + head_b
// ---------------------------------------------------------------------------
__global__ void k_head(const float* __restrict__ head_w,
                       const float* __restrict__ head_b,
                       float* __restrict__ out) {
    int b = threadIdx.x;
    if (b < BATCH) {
        float s = head_b[0];
#pragma unroll
        for (int w = 0; w < NUM_WIRES; ++w) {
            float f = 0.0f;
#pragma unroll
            for (int c = 0; c < NCHUNK; ++c)
                f += g_partial[(b * NCHUNK + c) * NUM_WIRES + w];
            s = fmaf(f, head_w[w], s);
        }
        out[b] = s;
    }
}

// ---------------------------------------------------------------------------
extern "C" void kernel_launch(void* const* d_in, const int* in_sizes, int n_in,
                              void* d_out, int out_size) {
    const float* state_re = (const float*)d_in[0];
    const float* state_im = (const float*)d_in[1];
    const float* params   = (const float*)d_in[2];
    const float* head_w   = (const float*)d_in[3];
    const float* head_b   = (const float*)d_in[4];
    float* out = (float*)d_out;

    cudaFuncSetAttribute(k_pass_low, cudaFuncAttributeMaxDynamicSharedMemorySize,
                         CHUNK * (int)sizeof(float2));

    const int ph_blocks = (BATCH * CHUNK) / PH_THREADS;   // 4096
    const int pl_blocks = BATCH * NCHUNK;                 // 1024
    const int shmem = CHUNK * (int)sizeof(float2);        // 128KB

    // layer 0
    k_pass_high_first<<<ph_blocks, PH_THREADS>>>(state_re, state_im, g_buf0, params);
    k_pass_low<<<pl_blocks, PL_THREADS, shmem>>>(g_buf0, g_buf1, params, 0, 0);
    // layer 1
    k_pass_high<<<ph_blocks, PH_THREADS>>>(g_buf1, params, 1);
    k_pass_low<<<pl_blocks, PL_THREADS, shmem>>>(g_buf1, g_buf0, params, 1, 0);
    // layer 2
    k_pass_high<<<ph_blocks, PH_THREADS>>>(g_buf0, params, 2);
    k_pass_low<<<pl_blocks, PL_THREADS, shmem>>>(g_buf0, g_buf1, params, 2, 1);

    k_head<<<1, 64>>>(head_w, head_b, out);
}